// round 10
// baseline (speedup 1.0000x reference)
#include <cuda_runtime.h>
#include <cstdint>

// delta_layer: out[b,t,:] = [ x, delta(x), delta(delta(x)) ]
// delta(y)[t] = 0.5*(y[c(t+1)]-y[c(t-1)]) + 0.25*(y[c(t+2)]-y[c(t-2)]), c = clamp [0,T-1]
// Shapes fixed: B=32, T=4096, D=256, window=2.
//
// Round-10: two consecutive 8-row tiles per block with REGISTER-RING CARRY.
// After tile A (rows t0..t0+7, shifting every iter) the 9-deep ring holds
// rows t0+4..t0+12 == (t1-4..t1+4) — the warm ring for tile B. One 24KB smem
// buffer, reused: after committing tile A's bulk store we only wait for the
// smem *read* to complete (wait_group.read), so A's DRAM write overlaps B's
// compute. Halves ring warm-ups (halo read amp 2.0x -> 1.5x) and per-block
// fixed costs at unchanged occupancy (24KB -> 9 blocks/SM).
// Interior rows use the fused 9-tap double-delta:
//   dd(t) = 0.0625(x[t-4]+x[t+4]) + 0.25(x[t-3]+x[t+3]) + 0.25(x[t-2]+x[t+2])
//         - 0.25(x[t-1]+x[t+1]) - 0.625 x[t]

#define B_N 32
#define T_N 4096
#define F2_N 128            // float2 per input row (256 floats)
#define OF2_N 384           // float2 per output row (768 floats)
#define L_N 8               // rows per tile
#define CHUNKS (T_N / L_N)  // 512
#define PAIRS (CHUNKS / 2)  // 256
#define OUT_BYTES (L_N * OF2_N * 8)   // 24576

__device__ __forceinline__ uint32_t smem_u32(const void* p) {
    uint32_t a;
    asm("{ .reg .u64 t; cvta.to.shared.u64 t, %1; cvt.u32.u64 %0, t; }"
        : "=r"(a) : "l"(p));
    return a;
}

__device__ __forceinline__ float2 f2_delta(float2 m2, float2 m1, float2 p1, float2 p2) {
    float2 r;
    r.x = 0.5f * (p1.x - m1.x) + 0.25f * (p2.x - m2.x);
    r.y = 0.5f * (p1.y - m1.y) + 0.25f * (p2.y - m2.y);
    return r;
}

__device__ __forceinline__ float dd9(float a0, float a1, float a2, float a3, float a4,
                                     float a5, float a6, float a7, float a8) {
    return 0.0625f * (a0 + a8) + 0.25f * (a1 + a7) + 0.25f * (a2 + a6)
         - 0.25f * (a3 + a5) - 0.625f * a4;
}

__global__ void __launch_bounds__(128, 9)
delta_layer_kernel(const float2* __restrict__ x, float2* __restrict__ out) {
    __shared__ alignas(128) float2 s_out[L_N * OF2_N];   // 24 KB output staging

    const int tid  = threadIdx.x;            // 0..127 = float2 channel column
    const int pair = blockIdx.x;              // 0..255
    const int b    = blockIdx.y;

    const float2* __restrict__ xb = x + (size_t)b * T_N * F2_N + tid;
    const uint32_t sout_a = smem_u32(s_out);

    float2 r[9];
    bool ring_valid = false;

#pragma unroll
    for (int tile = 0; tile < 2; ++tile) {
        const int chunk = pair * 2 + tile;    // 0..511
        const int t0    = chunk * L_N;

        if (chunk != 0 && chunk != CHUNKS - 1) {
            // ---- interior: ring -> smem tile -> bulk store ----
            if (!ring_valid) {
#pragma unroll
                for (int j = 0; j < 9; ++j)
                    r[j] = __ldg(xb + (size_t)(t0 - 4 + j) * F2_N);
            }

#pragma unroll
            for (int i = 0; i < L_N; ++i) {
                float2* orow = s_out + i * OF2_N + tid;
                orow[0]        = r[4];                             // x
                orow[F2_N]     = f2_delta(r[2], r[3], r[5], r[6]); // delta
                float2 dd;
                dd.x = dd9(r[0].x, r[1].x, r[2].x, r[3].x, r[4].x,
                           r[5].x, r[6].x, r[7].x, r[8].x);
                dd.y = dd9(r[0].y, r[1].y, r[2].y, r[3].y, r[4].y,
                           r[5].y, r[6].y, r[7].y, r[8].y);
                orow[2 * F2_N] = dd;                               // double delta

                // shift EVERY iteration so the ring carries into the next tile.
                // prefetch row t+5 = t0+i+5; max t0+12 <= 4092 for chunk <= 510.
#pragma unroll
                for (int j = 0; j < 8; ++j) r[j] = r[j + 1];
                r[8] = __ldg(xb + (size_t)(t0 + 5 + i) * F2_N);
            }
            ring_valid = true;   // ring now = rows (t0+8)-4 .. (t0+8)+4

            __syncthreads();
            if (tid == 0) {
                asm volatile("fence.proxy.async.shared::cta;" ::: "memory");
                float2* dst = out + ((size_t)b * T_N + t0) * OF2_N;
                asm volatile(
                    "cp.async.bulk.global.shared::cta.bulk_group [%0], [%1], %2;"
                    :: "l"(dst), "r"(sout_a), "r"((uint32_t)OUT_BYTES) : "memory");
                asm volatile("cp.async.bulk.commit_group;" ::: "memory");
                if (tile == 0) {
                    // only need the SMEM read side done before reuse
                    asm volatile("cp.async.bulk.wait_group.read 0;" ::: "memory");
                }
            }
            if (tile == 0) __syncthreads();   // smem safe to overwrite
        } else {
            // ---- edge path: generic clamped math, direct global stores ----
            float2* __restrict__ ob = out + (size_t)b * T_N * OF2_N + tid;

            auto LD = [&](int t) -> float2 {
                t = t < 0 ? 0 : (t > T_N - 1 ? T_N - 1 : t);
                return __ldg(xb + (size_t)t * F2_N);
            };
            auto DELTA_AT = [&](int sdx) -> float2 {
                sdx = sdx < 0 ? 0 : (sdx > T_N - 1 ? T_N - 1 : sdx);
                return f2_delta(LD(sdx - 2), LD(sdx - 1), LD(sdx + 1), LD(sdx + 2));
            };

            for (int i = 0; i < L_N; ++i) {
                const int t = t0 + i;
                const size_t orow = (size_t)t * OF2_N;
                ob[orow]            = LD(t);
                ob[orow + F2_N]     = DELTA_AT(t);
                ob[orow + 2 * F2_N] =
                    f2_delta(DELTA_AT(t - 2), DELTA_AT(t - 1),
                             DELTA_AT(t + 1), DELTA_AT(t + 2));
            }
            ring_valid = false;
        }
    }

    // drain all outstanding bulk stores before block exit
    if (tid == 0) {
        asm volatile("cp.async.bulk.wait_group 0;" ::: "memory");
    }
}

extern "C" void kernel_launch(void* const* d_in, const int* in_sizes, int n_in,
                              void* d_out, int out_size) {
    const float2* x = (const float2*)d_in[0];
    float2* out     = (float2*)d_out;
    // d_in[1] = window (always 2) — baked in.

    dim3 block(128, 1);
    dim3 grid(PAIRS, B_N);   // (256, 32) = 8192 blocks
    delta_layer_kernel<<<grid, block>>>(x, out);
}

// round 11
// speedup vs baseline: 1.0124x; 1.0124x over previous
#include <cuda_runtime.h>
#include <cstdint>

// delta_layer: out[b,t,:] = [ x, delta(x), delta(delta(x)) ]
// delta(y)[t] = 0.5*(y[c(t+1)]-y[c(t-1)]) + 0.25*(y[c(t+2)]-y[c(t-2)]), c = clamp [0,T-1]
// Shapes fixed: B=32, T=4096, D=256, window=2.
//
// Round-11 = Round-9 champion with ONE change: the block-exit wait is
// cp.async.bulk.wait_group.read (smem source read done) instead of full
// completion. The TMA engine finishes the global writes after CTA exit
// (CUTLASS epilogue precedent), so the block slot is released ~15-20%
// earlier -> faster block turnover -> more concurrently outstanding bulk
// stores feeding the DRAM controller.
//
// Structure: reads via per-thread 9-deep float2 register ring (__ldg, halo
// absorbed by L1/L2); writes staged in a 24KB smem tile and issued as ONE
// cp.async.bulk store (long same-direction write bursts). 9 blocks/SM.
// Interior rows use the fused 9-tap double-delta:
//   dd(t) = 0.0625(x[t-4]+x[t+4]) + 0.25(x[t-3]+x[t+3]) + 0.25(x[t-2]+x[t+2])
//         - 0.25(x[t-1]+x[t+1]) - 0.625 x[t]

#define B_N 32
#define T_N 4096
#define F2_N 128            // float2 per input row (256 floats)
#define OF2_N 384           // float2 per output row (768 floats)
#define L_N 8               // rows per tile
#define CHUNKS (T_N / L_N)  // 512
#define OUT_BYTES (L_N * OF2_N * 8)   // 24576

__device__ __forceinline__ uint32_t smem_u32(const void* p) {
    uint32_t a;
    asm("{ .reg .u64 t; cvta.to.shared.u64 t, %1; cvt.u32.u64 %0, t; }"
        : "=r"(a) : "l"(p));
    return a;
}

__device__ __forceinline__ float2 f2_delta(float2 m2, float2 m1, float2 p1, float2 p2) {
    float2 r;
    r.x = 0.5f * (p1.x - m1.x) + 0.25f * (p2.x - m2.x);
    r.y = 0.5f * (p1.y - m1.y) + 0.25f * (p2.y - m2.y);
    return r;
}

__device__ __forceinline__ float dd9(float a0, float a1, float a2, float a3, float a4,
                                     float a5, float a6, float a7, float a8) {
    return 0.0625f * (a0 + a8) + 0.25f * (a1 + a7) + 0.25f * (a2 + a6)
         - 0.25f * (a3 + a5) - 0.625f * a4;
}

__global__ void __launch_bounds__(128, 9)
delta_layer_kernel(const float2* __restrict__ x, float2* __restrict__ out) {
    __shared__ alignas(128) float2 s_out[L_N * OF2_N];   // 24 KB output staging

    const int tid   = threadIdx.x;           // 0..127 = float2 channel column
    const int chunk = blockIdx.x;             // 0..511
    const int b     = blockIdx.y;
    const int t0    = chunk * L_N;

    const float2* __restrict__ xb = x + (size_t)b * T_N * F2_N + tid;

    if (chunk != 0 && chunk != CHUNKS - 1) {
        // ---- interior: __ldg register ring -> smem tile -> ONE bulk store ----
        // ring r[j] = x[t0-4+j], all in-bounds for interior chunks
        float2 r[9];
#pragma unroll
        for (int j = 0; j < 9; ++j)
            r[j] = __ldg(xb + (size_t)(t0 - 4 + j) * F2_N);

#pragma unroll
        for (int i = 0; i < L_N; ++i) {
            float2* orow = s_out + i * OF2_N + tid;
            orow[0]        = r[4];                             // x
            orow[F2_N]     = f2_delta(r[2], r[3], r[5], r[6]); // delta
            float2 dd;
            dd.x = dd9(r[0].x, r[1].x, r[2].x, r[3].x, r[4].x, r[5].x, r[6].x, r[7].x, r[8].x);
            dd.y = dd9(r[0].y, r[1].y, r[2].y, r[3].y, r[4].y, r[5].y, r[6].y, r[7].y, r[8].y);
            orow[2 * F2_N] = dd;                               // double delta

            if (i < L_N - 1) {
#pragma unroll
                for (int j = 0; j < 8; ++j) r[j] = r[j + 1];
                // max index: t0+12 <= 4092 < T for interior chunks
                r[8] = __ldg(xb + (size_t)(t0 + 5 + i) * F2_N);
            }
        }
        __syncthreads();

        if (tid == 0) {
            asm volatile("fence.proxy.async.shared::cta;" ::: "memory");
            float2* dst = out + ((size_t)b * T_N + t0) * OF2_N;
            asm volatile(
                "cp.async.bulk.global.shared::cta.bulk_group [%0], [%1], %2;"
                :: "l"(dst), "r"(smem_u32(s_out)), "r"((uint32_t)OUT_BYTES) : "memory");
            asm volatile("cp.async.bulk.commit_group;" ::: "memory");
            // Only wait for the SMEM-read side; global writes complete after
            // CTA exit (CUTLASS epilogue pattern). Releases the block slot early.
            asm volatile("cp.async.bulk.wait_group.read 0;" ::: "memory");
        }
    } else {
        // ---- edge path: generic clamped math, direct global stores ----
        float2* __restrict__ ob = out + (size_t)b * T_N * OF2_N + tid;

        auto LD = [&](int t) -> float2 {
            t = t < 0 ? 0 : (t > T_N - 1 ? T_N - 1 : t);
            return __ldg(xb + (size_t)t * F2_N);
        };
        auto DELTA_AT = [&](int sdx) -> float2 {
            sdx = sdx < 0 ? 0 : (sdx > T_N - 1 ? T_N - 1 : sdx);
            return f2_delta(LD(sdx - 2), LD(sdx - 1), LD(sdx + 1), LD(sdx + 2));
        };

        for (int i = 0; i < L_N; ++i) {
            const int t = t0 + i;
            const size_t orow = (size_t)t * OF2_N;
            ob[orow]            = LD(t);
            ob[orow + F2_N]     = DELTA_AT(t);
            ob[orow + 2 * F2_N] =
                f2_delta(DELTA_AT(t - 2), DELTA_AT(t - 1), DELTA_AT(t + 1), DELTA_AT(t + 2));
        }
    }
}

extern "C" void kernel_launch(void* const* d_in, const int* in_sizes, int n_in,
                              void* d_out, int out_size) {
    const float2* x = (const float2*)d_in[0];
    float2* out     = (float2*)d_out;
    // d_in[1] = window (always 2) — baked in.

    dim3 block(128, 1);
    dim3 grid(CHUNKS, B_N);   // (512, 32) = 16384 blocks
    delta_layer_kernel<<<grid, block>>>(x, out);
}